// round 7
// baseline (speedup 1.0000x reference)
#include <cuda_runtime.h>
#include <cuda_fp16.h>
#include <cstdint>

// ---------------- Problem constants ----------------
#define CB   4
#define CL   512
#define CD   1024
#define CED  2048
#define CNS  16
#define CRK  64
#define CKC  4
#define CML  (CB*CL)        // 2048
#define BLED (CB*CL*CED)    // 4194304

// ---------------- Scratch ----------------
__device__ float  g_xz[CB*CL*2*CED];     // xz fp32 (x | z)
__device__ float  g_dbc[2*CML*96];       // split-K accumulators (fp32)
__device__ float  g_delta[2*BLED];       // softplus(delta) fp32
__device__ __half g_yh[2*BLED];          // scan output (half)
__device__ __half g_ych[BLED];           // combined (half)
__device__ __half g_xh[CML*CD];          // x as half
__device__ __half g_wh[7077888];
#define OW_IN   0
#define OW_OUT  4194304
#define OWX_F   6291456
#define OWX_B   6488064
#define OWDT_F  6684672
#define OWDT_B  6815744

// ---------------- helpers ----------------
__device__ __forceinline__ float softplusf(float x) {
    return fmaxf(x, 0.f) + log1pf(__expf(-fabsf(x)));
}
__device__ __forceinline__ float siluf(float x) {
    return x / (1.f + __expf(-x));
}
__device__ __forceinline__ float ex2f(float x) {
    float y; asm("ex2.approx.ftz.f32 %0, %1;" : "=f"(y) : "f"(x));
    return y;
}
__device__ __forceinline__ void cp16(uint32_t dst, const void* src) {
    asm volatile("cp.async.cg.shared.global [%0], [%1], 16;" :: "r"(dst), "l"(src));
}
__device__ __forceinline__ void ldsm4(uint32_t& r0, uint32_t& r1, uint32_t& r2, uint32_t& r3, uint32_t addr) {
    asm volatile("ldmatrix.sync.aligned.m8n8.x4.shared.b16 {%0,%1,%2,%3}, [%4];"
                 : "=r"(r0), "=r"(r1), "=r"(r2), "=r"(r3) : "r"(addr));
}
__device__ __forceinline__ void sts4h(uint32_t addr, __half a, __half b, __half c, __half d) {
    __half2 lo = __halves2half2(a, b), hi = __halves2half2(c, d);
    asm volatile("st.shared.v2.b32 [%0], {%1, %2};"
                 :: "r"(addr), "r"(*(uint32_t*)&lo), "r"(*(uint32_t*)&hi));
}

// ---------------- merged conversion + zero kernel ----------------
// segments (in float2 units):
// S0 x:1048576  S1 W_in:2097152  S2 W_out:1048576  S3 Wx:98304  S4 Wxb:98304
// S5 Wdt:65536  S6 Wdtb:65536  S7 dbc zeros:196608
__global__ void cvt_all_k(const float2* __restrict__ x,
                          const float2* __restrict__ win,  const float2* __restrict__ wout,
                          const float2* __restrict__ wx,   const float2* __restrict__ wxb,
                          const float2* __restrict__ wdt,  const float2* __restrict__ wdtb,
                          __half2* __restrict__ xh, __half2* __restrict__ wh,
                          float2* __restrict__ dbcz)
{
    int i = blockIdx.x * blockDim.x + threadIdx.x;
    if (i < 1048576) {
        float2 v = x[i]; xh[i] = __floats2half2_rn(v.x, v.y); return;
    }
    i -= 1048576;
    if (i < 2097152) {
        float2 v = win[i]; wh[OW_IN/2 + i] = __floats2half2_rn(v.x, v.y); return;
    }
    i -= 2097152;
    if (i < 1048576) {
        float2 v = wout[i]; wh[OW_OUT/2 + i] = __floats2half2_rn(v.x, v.y); return;
    }
    i -= 1048576;
    if (i < 98304) {
        float2 v = wx[i]; wh[OWX_F/2 + i] = __floats2half2_rn(v.x, v.y); return;
    }
    i -= 98304;
    if (i < 98304) {
        float2 v = wxb[i]; wh[OWX_B/2 + i] = __floats2half2_rn(v.x, v.y); return;
    }
    i -= 98304;
    if (i < 65536) {
        float2 v = wdt[i]; wh[OWDT_F/2 + i] = __floats2half2_rn(v.x, v.y); return;
    }
    i -= 65536;
    if (i < 65536) {
        float2 v = wdtb[i]; wh[OWDT_B/2 + i] = __floats2half2_rn(v.x, v.y); return;
    }
    i -= 65536;
    if (i < 196608) dbcz[i] = make_float2(0.f, 0.f);
}
#define CVT_TOTAL (1048576+2097152+1048576+98304+98304+65536+65536+196608)

// ================= FP16 tensor-core NT GEMM =================
// C[M,N] = A[M,K] * B[N,K]^T, fp32 accumulate. BM=128, BK=64, NS=2 cp.async ring,
// ldmatrix for both operands, one __syncthreads per k-tile.
// EPI: 0 none, 1 softplus(acc + bias[n]).
// DIRAX: 0 none; 1 dir=blockIdx.x (col0=0), split-K on z (atomic); 2 dir=blockIdx.z.
// AMODE: 0 A=half via cp.async; 1 A=fp32, cvt in loader; 2 A=conv+silu from xz.
#define LDKH 72
#define GNS  2
template<int BN, int EPI, int DIRAX, int AMODE>
__global__ void __launch_bounds__(2*(BN/32)*32)
gemm_f16(const void* __restrict__ Araw, int lda, size_t aStride,
         const __half* __restrict__ B0, const __half* __restrict__ B1, int ldb,
         float* __restrict__ C, int ldc, size_t cStride,
         int K, const float* __restrict__ bias0, const float* __restrict__ bias1,
         const float* __restrict__ cw0, const float* __restrict__ cb0,
         const float* __restrict__ cw1, const float* __restrict__ cb1)
{
    constexpr int BM = 128;
    constexpr int WARPS_N = BN/32;
    constexpr int THREADS = 2*WARPS_N*32;
    constexpr int STAGE_H = (BM+BN)*LDKH;
    extern __shared__ __half smh[];

    const int tid  = threadIdx.x;
    const int warp = tid >> 5, lane = tid & 31;
    const int wm = warp / WARPS_N, wn = warp % WARPS_N;
    const int g = lane >> 2, t = lane & 3;

    const int dir = (DIRAX==1) ? blockIdx.x : (DIRAX==2 ? blockIdx.z : 0);
    const int row0 = blockIdx.y * BM;
    const int col0 = (DIRAX==1) ? 0 : blockIdx.x * BN;
    const int nsplit = (DIRAX==1) ? gridDim.z : 1;
    const int Kc = K / nsplit;
    const int kbase = (DIRAX==1) ? blockIdx.z * Kc : 0;
    const int KT = Kc / 64;

    const __half* Beff = dir ? B1 : B0;
    float*        Ceff = C + (size_t)dir * cStride;
    const float*  bias = dir ? bias1 : bias0;
    const float*  cw   = dir ? cw1 : cw0;
    const float*  cb   = dir ? cb1 : cb0;

    float acc[4][4][4];
#pragma unroll
    for (int i = 0; i < 4; i++)
#pragma unroll
        for (int j = 0; j < 4; j++)
#pragma unroll
            for (int q = 0; q < 4; q++) acc[i][j][q] = 0.f;

    const uint32_t smem0 = (uint32_t)__cvta_generic_to_shared(smh);

    const uint32_t aLane = (uint32_t)(((wm*64 + (lane & 7) + ((lane >> 3) & 1) * 8) * LDKH
                                     + (lane >> 4) * 8) * 2);
    const uint32_t bLane = (uint32_t)((BM*LDKH
                                     + (wn*32 + (lane & 7) + ((lane >> 4) & 1) * 8) * LDKH
                                     + ((lane >> 3) & 1) * 8) * 2);

    auto load_tile = [&](int kt, int s) {
        __half* As = smh + s*STAGE_H;
        __half* Bs = As + BM*LDKH;
        const int k0 = kbase + kt*64;
        if (AMODE == 0) {
            const __half* Aeff = (const __half*)Araw + (size_t)dir * aStride;
#pragma unroll 2
            for (int i = tid; i < BM*8; i += THREADS) {
                int m = i >> 3, kq = (i & 7) << 3;
                cp16((uint32_t)__cvta_generic_to_shared(As + m*LDKH + kq),
                     Aeff + (size_t)(row0+m)*lda + k0 + kq);
            }
        } else if (AMODE == 1) {
            const float* Aeff = (const float*)Araw + (size_t)dir * aStride;
            for (int i = tid; i < BM*16; i += THREADS) {
                int m = i >> 4, kq = (i & 15) << 2;
                float4 v = *(const float4*)&Aeff[(size_t)(row0+m)*lda + k0 + kq];
                uint32_t dst = (uint32_t)__cvta_generic_to_shared(As + m*LDKH + kq);
                sts4h(dst, __float2half_rn(v.x), __float2half_rn(v.y),
                           __float2half_rn(v.z), __float2half_rn(v.w));
            }
        } else {  // AMODE == 2: conv+silu from xz (x part). K dim = channel e.
            const float4* xz4 = (const float4*)Araw;
            const float4* cw4 = (const float4*)cw;
            const float4* cb4 = (const float4*)cb;
            for (int i = tid; i < BM*16; i += THREADS) {
                int m = i >> 4;
                int e = k0 + ((i & 15) << 2);
                int r = row0 + m;
                int b = r >> 9, tt = r & 511;
                float4 w0 = cw4[e+0], w1 = cw4[e+1], w2 = cw4[e+2], w3 = cw4[e+3];
                float4 bi = cb4[e >> 2];
                float a0 = bi.x, a1 = bi.y, a2 = bi.z, a3 = bi.w;
#pragma unroll
                for (int j = 0; j < CKC; j++) {
                    int ts = tt - (CKC-1) + j;
                    if (ts >= 0) {
                        int tg = dir ? (CL-1-ts) : ts;
                        float4 v = xz4[(size_t)((b<<9) + tg)*1024 + (e >> 2)];
                        float t0 = (j==0)?w0.x:(j==1)?w0.y:(j==2)?w0.z:w0.w;
                        float t1 = (j==0)?w1.x:(j==1)?w1.y:(j==2)?w1.z:w1.w;
                        float t2 = (j==0)?w2.x:(j==1)?w2.y:(j==2)?w2.z:w2.w;
                        float t3 = (j==0)?w3.x:(j==1)?w3.y:(j==2)?w3.z:w3.w;
                        a0 = fmaf(t0, v.x, a0); a1 = fmaf(t1, v.y, a1);
                        a2 = fmaf(t2, v.z, a2); a3 = fmaf(t3, v.w, a3);
                    }
                }
                uint32_t dst = (uint32_t)__cvta_generic_to_shared(As + m*LDKH + ((i & 15) << 2));
                sts4h(dst, __float2half_rn(siluf(a0)), __float2half_rn(siluf(a1)),
                           __float2half_rn(siluf(a2)), __float2half_rn(siluf(a3)));
            }
        }
#pragma unroll 2
        for (int i = tid; i < BN*8; i += THREADS) {
            int n = i >> 3, kq = (i & 7) << 3;
            cp16((uint32_t)__cvta_generic_to_shared(Bs + n*LDKH + kq),
                 Beff + (size_t)(col0+n)*ldb + k0 + kq);
        }
    };

    auto comp = [&](int s) {
        const uint32_t base = smem0 + (uint32_t)(s*STAGE_H)*2u;
#pragma unroll
        for (int ks = 0; ks < 4; ks++) {
            const uint32_t kb = (uint32_t)(ks*16)*2u;
            uint32_t a[4][4], b[2][4];
#pragma unroll
            for (int mt = 0; mt < 4; mt++)
                ldsm4(a[mt][0], a[mt][1], a[mt][2], a[mt][3],
                      base + aLane + (uint32_t)(mt*16*LDKH)*2u + kb);
#pragma unroll
            for (int np = 0; np < 2; np++)
                ldsm4(b[np][0], b[np][1], b[np][2], b[np][3],
                      base + bLane + (uint32_t)(np*16*LDKH)*2u + kb);
#pragma unroll
            for (int mt = 0; mt < 4; mt++)
#pragma unroll
                for (int nt = 0; nt < 4; nt++) {
                    const uint32_t bb0 = b[nt>>1][(nt&1)*2 + 0];
                    const uint32_t bb1 = b[nt>>1][(nt&1)*2 + 1];
                    asm volatile(
                        "mma.sync.aligned.m16n8k16.row.col.f32.f16.f16.f32 "
                        "{%0,%1,%2,%3}, {%4,%5,%6,%7}, {%8,%9}, {%0,%1,%2,%3};"
                        : "+f"(acc[mt][nt][0]), "+f"(acc[mt][nt][1]),
                          "+f"(acc[mt][nt][2]), "+f"(acc[mt][nt][3])
                        : "r"(a[mt][0]), "r"(a[mt][1]), "r"(a[mt][2]), "r"(a[mt][3]),
                          "r"(bb0), "r"(bb1));
                }
        }
    };

    load_tile(0, 0);
    asm volatile("cp.async.commit_group;");

    for (int kt = 0; kt < KT; kt++) {
        asm volatile("cp.async.wait_group %0;" :: "n"(GNS-2));
        __syncthreads();
        if (kt + GNS - 1 < KT) load_tile(kt + GNS - 1, (kt + GNS - 1) % GNS);
        asm volatile("cp.async.commit_group;");
        comp(kt % GNS);
    }

    const bool use_atomic = (DIRAX == 1 && nsplit > 1);
#pragma unroll
    for (int mt = 0; mt < 4; mt++) {
        int row = row0 + wm*64 + mt*16 + g;
#pragma unroll
        for (int nt = 0; nt < 4; nt++) {
            int col = col0 + wn*32 + nt*8 + 2*t;
            float v0 = acc[mt][nt][0], v1 = acc[mt][nt][1];
            float v2 = acc[mt][nt][2], v3 = acc[mt][nt][3];
            if (EPI == 1) {
                v0 = softplusf(v0 + bias[col]);
                v1 = softplusf(v1 + bias[col+1]);
                v2 = softplusf(v2 + bias[col]);
                v3 = softplusf(v3 + bias[col+1]);
            }
            if (use_atomic) {
                atomicAdd(&Ceff[(size_t)row*ldc + col],       v0);
                atomicAdd(&Ceff[(size_t)row*ldc + col + 1],   v1);
                atomicAdd(&Ceff[(size_t)(row+8)*ldc + col],   v2);
                atomicAdd(&Ceff[(size_t)(row+8)*ldc + col+1], v3);
            } else {
                *(float2*)&Ceff[(size_t)row*ldc + col]     = make_float2(v0, v1);
                *(float2*)&Ceff[(size_t)(row+8)*ldc + col] = make_float2(v2, v3);
            }
        }
    }
}

// ---------------- selective scan with inline conv, both dirs --------------
#define SCAN_TC 16
__global__ void __launch_bounds__(128)
scan_kernel(const float* __restrict__ delta,
            const float* __restrict__ xz,
            const float* __restrict__ dbc,
            const float* __restrict__ A_log_f, const float* __restrict__ A_log_b,
            const float* __restrict__ Dp_f,    const float* __restrict__ Dp_b,
            const float* __restrict__ cw0, const float* __restrict__ cb0,
            const float* __restrict__ cw1, const float* __restrict__ cb1,
            __half* __restrict__ y)
{
    __shared__ float sD[SCAN_TC][128];
    __shared__ float sX[SCAN_TC][128];
    __shared__ float sZ[SCAN_TC][128];
    __shared__ float sB[SCAN_TC][CNS];
    __shared__ float sC[SCAN_TC][CNS];

    const int e   = blockIdx.x * 128 + threadIdx.x;
    const int b   = blockIdx.y;
    const int dir = blockIdx.z;
    const int tx  = threadIdx.x;

    const float*  dlt = delta + (size_t)dir * BLED;
    const float*  dbd = dbc   + (size_t)dir * CML * 96;
    __half*       yd  = y     + (size_t)dir * BLED;
    const float* A_log = dir ? A_log_b : A_log_f;
    const float* Dp    = dir ? Dp_b    : Dp_f;
    const float* cw    = dir ? cw1 : cw0;
    const float  cbias = (dir ? cb1 : cb0)[e];
    const float4 wv    = ((const float4*)cw)[e];

    float Areg[CNS];
#pragma unroll
    for (int n = 0; n < CNS; n++)
        Areg[n] = -__expf(A_log[e*CNS + n]) * 1.4426950408889634f;
    const float Dpe = Dp[e];

    float h[CNS];
#pragma unroll
    for (int n = 0; n < CNS; n++) h[n] = 0.f;
    float p1 = 0.f, p2 = 0.f, p3 = 0.f;   // conv window (raw inputs t-1,t-2,t-3)

    for (int t0 = 0; t0 < CL; t0 += SCAN_TC) {
        __syncthreads();
#pragma unroll
        for (int it = 0; it < SCAN_TC; it++) {
            int t = t0 + it;
            sD[it][tx] = dlt[(size_t)(b*CL + t) * CED + e];
            int tg = dir ? (CL-1-t) : t;
            sX[it][tx] = xz[((size_t)(b*CL + tg) << 12) + e];
            sZ[it][tx] = xz[((size_t)(b*CL + tg) << 12) + CED + e];
        }
        for (int j = tx; j < SCAN_TC*CNS; j += 128) {
            int it = j >> 4, n = j & (CNS-1);
            size_t r = (size_t)(b*CL + t0 + it) * 96;
            sB[it][n] = dbd[r + CRK + n];
            sC[it][n] = dbd[r + CRK + CNS + n];
        }
        __syncthreads();

#pragma unroll
        for (int it = 0; it < SCAN_TC; it++) {
            float xr = sX[it][tx];
            float cv = cbias;
            cv = fmaf(wv.x, p3, cv);
            cv = fmaf(wv.y, p2, cv);
            cv = fmaf(wv.z, p1, cv);
            cv = fmaf(wv.w, xr, cv);
            p3 = p2; p2 = p1; p1 = xr;
            float xv = siluf(cv);

            float d  = sD[it][tx];
            float dx = d * xv;
            float y0 = 0.f, y1 = 0.f, y2 = 0.f, y3 = 0.f;
#pragma unroll
            for (int n = 0; n < CNS; n += 4) {
                float dA0 = ex2f(d * Areg[n+0]);
                float dA1 = ex2f(d * Areg[n+1]);
                float dA2 = ex2f(d * Areg[n+2]);
                float dA3 = ex2f(d * Areg[n+3]);
                h[n+0] = fmaf(dA0, h[n+0], dx * sB[it][n+0]);
                h[n+1] = fmaf(dA1, h[n+1], dx * sB[it][n+1]);
                h[n+2] = fmaf(dA2, h[n+2], dx * sB[it][n+2]);
                h[n+3] = fmaf(dA3, h[n+3], dx * sB[it][n+3]);
                y0 = fmaf(h[n+0], sC[it][n+0], y0);
                y1 = fmaf(h[n+1], sC[it][n+1], y1);
                y2 = fmaf(h[n+2], sC[it][n+2], y2);
                y3 = fmaf(h[n+3], sC[it][n+3], y3);
            }
            float zv = sZ[it][tx];
            float yo = ((y0+y1) + (y2+y3)) + Dpe * xv;
            yd[(size_t)(b*CL + t0 + it)*CED + e] = __float2half_rn(yo * siluf(zv));
        }
    }
}

// ---------------- combine (half2 in, half2 out) ------------------
__global__ void combine_kernel(const __half2* __restrict__ y0,
                               const __half2* __restrict__ y1,
                               __half2* __restrict__ yc)
{
    int idx = blockIdx.x * blockDim.x + threadIdx.x;
    int e2 = idx & (CED/2 - 1);
    int t  = (idx >> 10) & (CL-1);
    int b  = idx >> 19;
    float2 a  = __half22float2(y0[idx]);
    float2 bb = __half22float2(y1[(size_t)(b*CL + (CL-1-t))*(CED/2) + e2]);
    yc[idx] = __floats2half2_rn(0.5f*(a.x + bb.x), 0.5f*(a.y + bb.y));
}

// ---------------- launch ----------------
extern "C" void kernel_launch(void* const* d_in, const int* in_sizes, int n_in,
                              void* d_out, int out_size)
{
    const float* x      = (const float*)d_in[0];
    const float* W_in   = (const float*)d_in[1];
    const float* conv_w = (const float*)d_in[2];
    const float* conv_b = (const float*)d_in[3];
    const float* Wx     = (const float*)d_in[4];
    const float* Wdt    = (const float*)d_in[5];
    const float* b_dt   = (const float*)d_in[6];
    const float* A_log  = (const float*)d_in[7];
    const float* Dp     = (const float*)d_in[8];
    const float* conv_w_b = (const float*)d_in[9];
    const float* conv_b_b = (const float*)d_in[10];
    const float* Wx_b   = (const float*)d_in[11];
    const float* Wdt_b  = (const float*)d_in[12];
    const float* b_dt_b = (const float*)d_in[13];
    const float* A_log_b= (const float*)d_in[14];
    const float* Dp_b   = (const float*)d_in[15];
    const float* W_out  = (const float*)d_in[16];
    float* out = (float*)d_out;

    float *p_xz, *p_dbc, *p_delta;
    __half *p_yh, *p_ych, *p_xh, *p_wh;
    cudaGetSymbolAddress((void**)&p_xz,    g_xz);
    cudaGetSymbolAddress((void**)&p_dbc,   g_dbc);
    cudaGetSymbolAddress((void**)&p_delta, g_delta);
    cudaGetSymbolAddress((void**)&p_yh,    g_yh);
    cudaGetSymbolAddress((void**)&p_ych,   g_ych);
    cudaGetSymbolAddress((void**)&p_xh,    g_xh);
    cudaGetSymbolAddress((void**)&p_wh,    g_wh);

    constexpr int SMEM128 = GNS*(128+128)*LDKH*2;   // 73728
    constexpr int SMEM96  = GNS*(128+96) *LDKH*2;   // 64512
    cudaFuncSetAttribute(gemm_f16<128,0,0,0>, cudaFuncAttributeMaxDynamicSharedMemorySize, SMEM128);
    cudaFuncSetAttribute(gemm_f16<128,1,2,1>, cudaFuncAttributeMaxDynamicSharedMemorySize, SMEM128);
    cudaFuncSetAttribute(gemm_f16<96,0,1,2>,  cudaFuncAttributeMaxDynamicSharedMemorySize, SMEM96);

    // 0) one merged conversion/zero pass
    cvt_all_k<<<(CVT_TOTAL + 255)/256, 256>>>(
        (const float2*)x, (const float2*)W_in, (const float2*)W_out,
        (const float2*)Wx, (const float2*)Wx_b, (const float2*)Wdt, (const float2*)Wdt_b,
        (__half2*)p_xh, (__half2*)p_wh, (float2*)p_dbc);

    // 1) xz = x @ W_in^T : [2048,1024] x [4096,1024]^T
    gemm_f16<128,0,0,0><<<dim3(32,16,1), 256, SMEM128>>>(
        p_xh, CD, 0, p_wh+OW_IN, p_wh+OW_IN, CD, p_xz, 2*CED, 0, CD,
        nullptr, nullptr, nullptr, nullptr, nullptr, nullptr);

    // 2) dbc = conv_silu(xz) @ Wx^T (conv fused into A-loader; both dirs, split-K=8)
    gemm_f16<96,0,1,2><<<dim3(2,16,8), 192, SMEM96>>>(
        p_xz, 0, 0, p_wh+OWX_F, p_wh+OWX_B, CED,
        p_dbc, 96, (size_t)CML*96, CED, nullptr, nullptr,
        conv_w, conv_b, conv_w_b, conv_b_b);

    // 3) delta = softplus(dbc[:, :64] @ Wdt^T + b_dt)  (fp32 A cvt in loader)
    gemm_f16<128,1,2,1><<<dim3(16,16,2), 256, SMEM128>>>(
        p_dbc, 96, (size_t)CML*96, p_wh+OWDT_F, p_wh+OWDT_B, CRK,
        p_delta, CED, (size_t)BLED, CRK, b_dt, b_dt_b,
        nullptr, nullptr, nullptr, nullptr);

    // 4) selective scan + inline conv + gating, both dirs -> half
    scan_kernel<<<dim3(CED/128, CB, 2), 128>>>(
        p_delta, p_xz, p_dbc, A_log, A_log_b, Dp, Dp_b,
        conv_w, conv_b, conv_w_b, conv_b_b, p_yh);

    // 5) combine -> half
    combine_kernel<<<(BLED/2)/256, 256>>>(
        (const __half2*)p_yh, (const __half2*)(p_yh + BLED), (__half2*)p_ych);

    // 6) out = yc @ W_out^T : [2048,2048] x [1024,2048]^T
    gemm_f16<128,0,0,0><<<dim3(8,16,1), 256, SMEM128>>>(
        p_ych, CED, 0, p_wh+OW_OUT, p_wh+OW_OUT, CED, out, CD, 0, CED,
        nullptr, nullptr, nullptr, nullptr, nullptr, nullptr);
}

// round 8
// speedup vs baseline: 1.2922x; 1.2922x over previous
#include <cuda_runtime.h>
#include <cuda_fp16.h>
#include <cstdint>

// ---------------- Problem constants ----------------
#define CB   4
#define CL   512
#define CD   1024
#define CED  2048
#define CNS  16
#define CRK  64
#define CKC  4
#define CML  (CB*CL)        // 2048
#define BLED (CB*CL*CED)    // 4194304

// ---------------- Scratch ----------------
__device__ float  g_xz[CB*CL*2*CED];     // xz fp32
__device__ __half g_xch[2*BLED];         // conv+silu output (half)
__device__ float  g_dbc[2*CML*96];       // split-K accumulators (fp32)
__device__ __half g_dbch[2*CML*96];      // dbc as half
__device__ float  g_delta[2*BLED];       // softplus(delta) fp32
__device__ float  g_y[2*BLED];           // scan output fp32
__device__ __half g_ych[BLED];           // combined (half)
__device__ __half g_xh[CML*CD];          // x as half
__device__ __half g_wh[7077888];
#define OW_IN   0
#define OW_OUT  4194304
#define OWX_F   6291456
#define OWX_B   6488064
#define OWDT_F  6684672
#define OWDT_B  6815744

// ---------------- helpers ----------------
__device__ __forceinline__ float softplusf(float x) {
    return fmaxf(x, 0.f) + log1pf(__expf(-fabsf(x)));
}
__device__ __forceinline__ float siluf(float x) {
    return x / (1.f + __expf(-x));
}
__device__ __forceinline__ float ex2f(float x) {
    float y; asm("ex2.approx.ftz.f32 %0, %1;" : "=f"(y) : "f"(x));
    return y;
}
__device__ __forceinline__ void cp16(uint32_t dst, const void* src) {
    asm volatile("cp.async.cg.shared.global [%0], [%1], 16;" :: "r"(dst), "l"(src));
}
__device__ __forceinline__ void ldsm4(uint32_t& r0, uint32_t& r1, uint32_t& r2, uint32_t& r3, uint32_t addr) {
    asm volatile("ldmatrix.sync.aligned.m8n8.x4.shared.b16 {%0,%1,%2,%3}, [%4];"
                 : "=r"(r0), "=r"(r1), "=r"(r2), "=r"(r3) : "r"(addr));
}
__device__ __forceinline__ uint2 f4h(float4 v) {
    __half2 lo = __floats2half2_rn(v.x, v.y);
    __half2 hi = __floats2half2_rn(v.z, v.w);
    return make_uint2(*(uint32_t*)&lo, *(uint32_t*)&hi);
}
template<bool B> struct BC { static constexpr bool v = B; };

// ---------------- merged conversion + zero (float4 / half4) ----------------
// segments (float4 units): x 524288 | W_in 1048576 | W_out 524288 | Wx 49152
// | Wxb 49152 | Wdt 32768 | Wdtb 32768 | dbc-zero 98304
#define CVT_TOTAL (524288+1048576+524288+49152+49152+32768+32768+98304)
__global__ void cvt_all_k(const float4* __restrict__ x,
                          const float4* __restrict__ win,  const float4* __restrict__ wout,
                          const float4* __restrict__ wx,   const float4* __restrict__ wxb,
                          const float4* __restrict__ wdt,  const float4* __restrict__ wdtb,
                          uint2* __restrict__ xh, uint2* __restrict__ wh,
                          float4* __restrict__ dbcz)
{
    int i = blockIdx.x * blockDim.x + threadIdx.x;
    if (i < 524288)  { xh[i] = f4h(x[i]); return; }                 i -= 524288;
    if (i < 1048576) { wh[OW_IN/4  + i] = f4h(win[i]);  return; }   i -= 1048576;
    if (i < 524288)  { wh[OW_OUT/4 + i] = f4h(wout[i]); return; }   i -= 524288;
    if (i < 49152)   { wh[OWX_F/4  + i] = f4h(wx[i]);   return; }   i -= 49152;
    if (i < 49152)   { wh[OWX_B/4  + i] = f4h(wxb[i]);  return; }   i -= 49152;
    if (i < 32768)   { wh[OWDT_F/4 + i] = f4h(wdt[i]);  return; }   i -= 32768;
    if (i < 32768)   { wh[OWDT_B/4 + i] = f4h(wdtb[i]); return; }   i -= 32768;
    if (i < 98304)   dbcz[i] = make_float4(0.f, 0.f, 0.f, 0.f);
}

__global__ void f2h_k(const float2* __restrict__ in, __half2* __restrict__ out, int n2) {
    int i = blockIdx.x * blockDim.x + threadIdx.x;
    if (i < n2) {
        float2 v = in[i];
        out[i] = __floats2half2_rn(v.x, v.y);
    }
}

// ================= FP16 tensor-core NT GEMM (R5 config) =================
// C[M,N] = A[M,K] * B[N,K]^T, fp32 accumulate. BM=128, BK=64, 2-stage cp.async.
// EPI: 0 none, 1 softplus(acc + bias[n]).
// DIRAX: 0 none; 1 dir=blockIdx.x (col0=0), split-K on z (atomic); 2 dir=blockIdx.z.
#define LDKH 72
template<int BN, int EPI, int DIRAX>
__global__ void __launch_bounds__(2*(BN/32)*32)
gemm_f16(const __half* __restrict__ A, int lda, size_t aStride,
         const __half* __restrict__ B0, const __half* __restrict__ B1, int ldb,
         float* __restrict__ C, int ldc, size_t cStride,
         int K, const float* __restrict__ bias0, const float* __restrict__ bias1)
{
    constexpr int BM = 128;
    constexpr int WARPS_N = BN/32;
    constexpr int THREADS = 2*WARPS_N*32;
    constexpr int STAGE_H = (BM+BN)*LDKH;
    extern __shared__ __half smh[];

    const int tid  = threadIdx.x;
    const int warp = tid >> 5, lane = tid & 31;
    const int wm = warp / WARPS_N, wn = warp % WARPS_N;
    const int g = lane >> 2, t = lane & 3;

    const int dir = (DIRAX==1) ? blockIdx.x : (DIRAX==2 ? blockIdx.z : 0);
    const int row0 = blockIdx.y * BM;
    const int col0 = (DIRAX==1) ? 0 : blockIdx.x * BN;
    const int nsplit = (DIRAX==1) ? gridDim.z : 1;
    const int Kc = K / nsplit;
    const int kbase = (DIRAX==1) ? blockIdx.z * Kc : 0;
    const int KT = Kc / 64;

    const __half* Aeff = A + (size_t)dir * aStride;
    const __half* Beff = dir ? B1 : B0;
    float*        Ceff = C + (size_t)dir * cStride;
    const float*  bias = dir ? bias1 : bias0;

    float acc[4][4][4];
#pragma unroll
    for (int i = 0; i < 4; i++)
#pragma unroll
        for (int j = 0; j < 4; j++)
#pragma unroll
            for (int q = 0; q < 4; q++) acc[i][j][q] = 0.f;

    const uint32_t smem0 = (uint32_t)__cvta_generic_to_shared(smh);

    const uint32_t aLane = (uint32_t)(((wm*64 + (lane & 7) + ((lane >> 3) & 1) * 8) * LDKH
                                     + (lane >> 4) * 8) * 2);
    const uint32_t bLane = (uint32_t)((BM*LDKH + (wn*32 + g) * LDKH + 2*t) * 2);

    auto load_tile = [&](int kt, int s) {
        __half* As = smh + s*STAGE_H;
        __half* Bs = As + BM*LDKH;
        const int k0 = kbase + kt*64;
#pragma unroll 2
        for (int i = tid; i < BM*8; i += THREADS) {
            int m = i >> 3, kq = (i & 7) << 3;
            cp16((uint32_t)__cvta_generic_to_shared(As + m*LDKH + kq),
                 Aeff + (size_t)(row0+m)*lda + k0 + kq);
        }
#pragma unroll 2
        for (int i = tid; i < BN*8; i += THREADS) {
            int n = i >> 3, kq = (i & 7) << 3;
            cp16((uint32_t)__cvta_generic_to_shared(Bs + n*LDKH + kq),
                 Beff + (size_t)(col0+n)*ldb + k0 + kq);
        }
        asm volatile("cp.async.commit_group;");
    };

    auto comp = [&](int s) {
        const uint32_t base = smem0 + (uint32_t)(s*STAGE_H)*2u;
#pragma unroll
        for (int ks = 0; ks < 4; ks++) {
            const uint32_t kb = (uint32_t)(ks*16)*2u;
            uint32_t a[4][4];
#pragma unroll
            for (int mt = 0; mt < 4; mt++)
                ldsm4(a[mt][0], a[mt][1], a[mt][2], a[mt][3],
                      base + aLane + (uint32_t)(mt*16*LDKH)*2u + kb);
#pragma unroll
            for (int nt = 0; nt < 4; nt++) {
                uint32_t b0, b1;
                const uint32_t baddr = base + bLane + (uint32_t)(nt*8*LDKH)*2u + kb;
                asm volatile("ld.shared.b32 %0, [%1];" : "=r"(b0) : "r"(baddr));
                asm volatile("ld.shared.b32 %0, [%1];" : "=r"(b1) : "r"(baddr + 16u));
#pragma unroll
                for (int mt = 0; mt < 4; mt++)
                    asm volatile(
                        "mma.sync.aligned.m16n8k16.row.col.f32.f16.f16.f32 "
                        "{%0,%1,%2,%3}, {%4,%5,%6,%7}, {%8,%9}, {%0,%1,%2,%3};"
                        : "+f"(acc[mt][nt][0]), "+f"(acc[mt][nt][1]),
                          "+f"(acc[mt][nt][2]), "+f"(acc[mt][nt][3])
                        : "r"(a[mt][0]), "r"(a[mt][1]), "r"(a[mt][2]), "r"(a[mt][3]),
                          "r"(b0), "r"(b1));
            }
        }
    };

    load_tile(0, 0);
    for (int kt = 0; kt < KT; kt++) {
        if (kt + 1 < KT) {
            load_tile(kt + 1, (kt + 1) & 1);
            asm volatile("cp.async.wait_group 1;");
        } else {
            asm volatile("cp.async.wait_group 0;");
        }
        __syncthreads();
        comp(kt & 1);
        __syncthreads();
    }

    const bool use_atomic = (DIRAX == 1 && nsplit > 1);
#pragma unroll
    for (int mt = 0; mt < 4; mt++) {
        int row = row0 + wm*64 + mt*16 + g;
#pragma unroll
        for (int nt = 0; nt < 4; nt++) {
            int col = col0 + wn*32 + nt*8 + 2*t;
            float v0 = acc[mt][nt][0], v1 = acc[mt][nt][1];
            float v2 = acc[mt][nt][2], v3 = acc[mt][nt][3];
            if (EPI == 1) {
                v0 = softplusf(v0 + bias[col]);
                v1 = softplusf(v1 + bias[col+1]);
                v2 = softplusf(v2 + bias[col]);
                v3 = softplusf(v3 + bias[col+1]);
            }
            if (use_atomic) {
                atomicAdd(&Ceff[(size_t)row*ldc + col],       v0);
                atomicAdd(&Ceff[(size_t)row*ldc + col + 1],   v1);
                atomicAdd(&Ceff[(size_t)(row+8)*ldc + col],   v2);
                atomicAdd(&Ceff[(size_t)(row+8)*ldc + col+1], v3);
            } else {
                *(float2*)&Ceff[(size_t)row*ldc + col]     = make_float2(v0, v1);
                *(float2*)&Ceff[(size_t)(row+8)*ldc + col] = make_float2(v2, v3);
            }
        }
    }
}

// ---------------- vectorized causal depthwise conv + SiLU -> half ----------
__global__ void conv_silu_kernel(const float4* __restrict__ xz4,
                                 const float4* __restrict__ cw0, const float4* __restrict__ cb0,
                                 const float4* __restrict__ cw1, const float4* __restrict__ cb1,
                                 uint2* __restrict__ xch)
{
    int idx = blockIdx.x * blockDim.x + threadIdx.x;   // over 2*BLED/4 = 2^21
    int e4  = idx & 511;
    int t   = (idx >> 9) & 511;
    int b   = (idx >> 18) & 3;
    int dir = idx >> 20;

    const float4* cw = dir ? cw1 : cw0;
    float4 bi = (dir ? cb1 : cb0)[e4];
    float4 w0 = cw[e4*4+0], w1 = cw[e4*4+1], w2 = cw[e4*4+2], w3 = cw[e4*4+3];
    float a0 = bi.x, a1 = bi.y, a2 = bi.z, a3 = bi.w;
#pragma unroll
    for (int j = 0; j < 4; j++) {
        int ts = t - 3 + j;
        if (ts >= 0) {
            int tg = dir ? (511 - ts) : ts;
            float4 v = xz4[(size_t)((b << 9) + tg) * 1024 + e4];
            float c0 = (j==0)?w0.x:(j==1)?w0.y:(j==2)?w0.z:w0.w;
            float c1 = (j==0)?w1.x:(j==1)?w1.y:(j==2)?w1.z:w1.w;
            float c2 = (j==0)?w2.x:(j==1)?w2.y:(j==2)?w2.z:w2.w;
            float c3 = (j==0)?w3.x:(j==1)?w3.y:(j==2)?w3.z:w3.w;
            a0 = fmaf(c0, v.x, a0); a1 = fmaf(c1, v.y, a1);
            a2 = fmaf(c2, v.z, a2); a3 = fmaf(c3, v.w, a3);
        }
    }
    __half2 lo = __floats2half2_rn(siluf(a0), siluf(a1));
    __half2 hi = __floats2half2_rn(siluf(a2), siluf(a3));
    xch[idx] = make_uint2(*(uint32_t*)&lo, *(uint32_t*)&hi);
}

// ---------------- selective scan (fast-exp power chain w/ fallback) --------
#define SCAN_TC 16
__global__ void __launch_bounds__(128)
scan_kernel(const float* __restrict__ delta,
            const __half* __restrict__ xc,
            const float* __restrict__ dbc,
            const float* __restrict__ xz,
            const float* __restrict__ A_log_f, const float* __restrict__ A_log_b,
            const float* __restrict__ Dp_f,    const float* __restrict__ Dp_b,
            float* __restrict__ y)
{
    __shared__ float sD[SCAN_TC][128];
    __shared__ float sX[SCAN_TC][128];
    __shared__ float sZ[SCAN_TC][128];
    __shared__ float sB[SCAN_TC][CNS];
    __shared__ float sC[SCAN_TC][CNS];

    const int e   = blockIdx.x * 128 + threadIdx.x;
    const int b   = blockIdx.y;
    const int dir = blockIdx.z;
    const int tx  = threadIdx.x;

    const float*  dlt = delta + (size_t)dir * BLED;
    const __half* xcd = xc    + (size_t)dir * BLED;
    const float*  dbd = dbc   + (size_t)dir * CML * 96;
    float*        yd  = y     + (size_t)dir * BLED;
    const float* A_log = dir ? A_log_b : A_log_f;
    const float* Dp    = dir ? Dp_b    : Dp_f;

    float Areg[CNS];
    bool fastok = true;
#pragma unroll
    for (int n = 0; n < CNS; n++) {
        float a = -__expf(A_log[e*CNS + n]);
        Areg[n] = a * 1.4426950408889634f;
        fastok = fastok && (fabsf(a + (float)(n+1)) < 1e-3f * (float)(n+1));
    }
    const bool fastA = __syncthreads_and(fastok);
    const float Dpe = Dp[e];

    float h[CNS];
#pragma unroll
    for (int n = 0; n < CNS; n++) h[n] = 0.f;

    auto run = [&](auto FC) {
        constexpr bool FAST = decltype(FC)::v;
        for (int t0 = 0; t0 < CL; t0 += SCAN_TC) {
            __syncthreads();
#pragma unroll
            for (int it = 0; it < SCAN_TC; it++) {
                int t = t0 + it;
                size_t r = (size_t)(b*CL + t) * CED + e;
                sD[it][tx] = dlt[r];
                sX[it][tx] = __half2float(xcd[r]);
                int tz = dir ? (CL-1-t) : t;
                sZ[it][tx] = xz[((size_t)(b*CL + tz) << 12) + CED + e];
            }
            for (int j = tx; j < SCAN_TC*CNS; j += 128) {
                int it = j >> 4, n = j & (CNS-1);
                size_t r = (size_t)(b*CL + t0 + it) * 96;
                sB[it][n] = dbd[r + CRK + n];
                sC[it][n] = dbd[r + CRK + CNS + n];
            }
            __syncthreads();

#pragma unroll
            for (int it = 0; it < SCAN_TC; it++) {
                float d  = sD[it][tx];
                float xv = sX[it][tx];
                float dx = d * xv;
                float dA[CNS];
                if (FAST) {
                    float r1 = ex2f(-1.4426950408889634f * d);   // exp(-d)
                    float r2 = r1*r1, r3 = r2*r1, r4 = r2*r2;
                    float r8 = r4*r4, r12 = r8*r4;
                    dA[0]=r1;      dA[1]=r2;      dA[2]=r3;      dA[3]=r4;
                    dA[4]=r4*r1;   dA[5]=r4*r2;   dA[6]=r4*r3;   dA[7]=r8;
                    dA[8]=r8*r1;   dA[9]=r8*r2;   dA[10]=r8*r3;  dA[11]=r8*r4;
                    dA[12]=r12*r1; dA[13]=r12*r2; dA[14]=r12*r3; dA[15]=r8*r8;
                } else {
#pragma unroll
                    for (int n = 0; n < CNS; n++) dA[n] = ex2f(d * Areg[n]);
                }
                float y0 = 0.f, y1 = 0.f, y2 = 0.f, y3 = 0.f;
#pragma unroll
                for (int n = 0; n < CNS; n += 4) {
                    h[n+0] = fmaf(dA[n+0], h[n+0], dx * sB[it][n+0]);
                    h[n+1] = fmaf(dA[n+1], h[n+1], dx * sB[it][n+1]);
                    h[n+2] = fmaf(dA[n+2], h[n+2], dx * sB[it][n+2]);
                    h[n+3] = fmaf(dA[n+3], h[n+3], dx * sB[it][n+3]);
                    y0 = fmaf(h[n+0], sC[it][n+0], y0);
                    y1 = fmaf(h[n+1], sC[it][n+1], y1);
                    y2 = fmaf(h[n+2], sC[it][n+2], y2);
                    y3 = fmaf(h[n+3], sC[it][n+3], y3);
                }
                float zv = sZ[it][tx];
                float yo = ((y0+y1) + (y2+y3)) + Dpe * xv;
                yd[(size_t)(b*CL + t0 + it)*CED + e] = yo * siluf(zv);
            }
        }
    };
    if (fastA) run(BC<true>{});
    else       run(BC<false>{});
}

// ---------------- combine (fp32 in, half out) ------------------
__global__ void combine_kernel(const float* __restrict__ y0,
                               const float* __restrict__ y1,
                               __half* __restrict__ yc)
{
    int idx = blockIdx.x * blockDim.x + threadIdx.x;
    int e = idx & (CED-1);
    int t = (idx >> 11) & (CL-1);
    int b = idx >> 20;
    float a  = y0[idx];
    float bb = y1[(size_t)(b*CL + (CL-1-t))*CED + e];
    yc[idx] = __float2half_rn(0.5f * (a + bb));
}

// ---------------- launch ----------------
extern "C" void kernel_launch(void* const* d_in, const int* in_sizes, int n_in,
                              void* d_out, int out_size)
{
    const float* x      = (const float*)d_in[0];
    const float* W_in   = (const float*)d_in[1];
    const float* conv_w = (const float*)d_in[2];
    const float* conv_b = (const float*)d_in[3];
    const float* Wx     = (const float*)d_in[4];
    const float* Wdt    = (const float*)d_in[5];
    const float* b_dt   = (const float*)d_in[6];
    const float* A_log  = (const float*)d_in[7];
    const float* Dp     = (const float*)d_in[8];
    const float* conv_w_b = (const float*)d_in[9];
    const float* conv_b_b = (const float*)d_in[10];
    const float* Wx_b   = (const float*)d_in[11];
    const float* Wdt_b  = (const float*)d_in[12];
    const float* b_dt_b = (const float*)d_in[13];
    const float* A_log_b= (const float*)d_in[14];
    const float* Dp_b   = (const float*)d_in[15];
    const float* W_out  = (const float*)d_in[16];
    float* out = (float*)d_out;

    float *p_xz, *p_dbc, *p_delta, *p_y;
    __half *p_xch, *p_dbch, *p_ych, *p_xh, *p_wh;
    cudaGetSymbolAddress((void**)&p_xz,    g_xz);
    cudaGetSymbolAddress((void**)&p_xch,   g_xch);
    cudaGetSymbolAddress((void**)&p_dbc,   g_dbc);
    cudaGetSymbolAddress((void**)&p_dbch,  g_dbch);
    cudaGetSymbolAddress((void**)&p_delta, g_delta);
    cudaGetSymbolAddress((void**)&p_y,     g_y);
    cudaGetSymbolAddress((void**)&p_ych,   g_ych);
    cudaGetSymbolAddress((void**)&p_xh,    g_xh);
    cudaGetSymbolAddress((void**)&p_wh,    g_wh);

    constexpr int SMEM128 = 2*(128+128)*LDKH*2;   // 73728
    constexpr int SMEM96  = 2*(128+96) *LDKH*2;   // 64512
    cudaFuncSetAttribute(gemm_f16<128,0,0>, cudaFuncAttributeMaxDynamicSharedMemorySize, SMEM128);
    cudaFuncSetAttribute(gemm_f16<128,1,2>, cudaFuncAttributeMaxDynamicSharedMemorySize, SMEM128);
    cudaFuncSetAttribute(gemm_f16<96,0,1>,  cudaFuncAttributeMaxDynamicSharedMemorySize, SMEM96);

    // 0) one merged conversion/zero pass (float4)
    cvt_all_k<<<(CVT_TOTAL + 255)/256, 256>>>(
        (const float4*)x, (const float4*)W_in, (const float4*)W_out,
        (const float4*)Wx, (const float4*)Wx_b, (const float4*)Wdt, (const float4*)Wdt_b,
        (uint2*)p_xh, (uint2*)p_wh, (float4*)p_dbc);

    // 1) xz = x @ W_in^T : [2048,1024] x [4096,1024]^T
    gemm_f16<128,0,0><<<dim3(32,16,1), 256, SMEM128>>>(
        p_xh, CD, 0, p_wh+OW_IN, p_wh+OW_IN, CD, p_xz, 2*CED, 0, CD, nullptr, nullptr);

    // 2) conv + silu (both dirs, vectorized) -> half
    conv_silu_kernel<<<(2*BLED/4)/256, 256>>>(
        (const float4*)p_xz, (const float4*)conv_w, (const float4*)conv_b,
        (const float4*)conv_w_b, (const float4*)conv_b_b, (uint2*)p_xch);

    // 3) dbc = xc @ Wx^T (both dirs, split-K=8 atomic)
    gemm_f16<96,0,1><<<dim3(2,16,8), 192, SMEM96>>>(
        p_xch, CED, (size_t)BLED, p_wh+OWX_F, p_wh+OWX_B, CED,
        p_dbc, 96, (size_t)CML*96, CED, nullptr, nullptr);

    // 3b) dbc -> half
    f2h_k<<<(2*CML*96/2 + 255)/256, 256>>>((const float2*)p_dbc, (__half2*)p_dbch, 2*CML*96/2);

    // 4) delta = softplus(dbc[:, :64] @ Wdt^T + b_dt)  (both dirs)
    gemm_f16<128,1,2><<<dim3(16,16,2), 256, SMEM128>>>(
        p_dbch, 96, (size_t)CML*96, p_wh+OWDT_F, p_wh+OWDT_B, CRK,
        p_delta, CED, (size_t)BLED, CRK, b_dt, b_dt_b);

    // 5) selective scan + gating, both dirs (fast-exp)
    scan_kernel<<<dim3(CED/128, CB, 2), 128>>>(
        p_delta, p_xch, p_dbc, p_xz, A_log, A_log_b, Dp, Dp_b, p_y);

    // 6) combine -> half
    combine_kernel<<<BLED/256, 256>>>(p_y, p_y + BLED, p_ych);

    // 7) out = yc @ W_out^T : [2048,2048] x [1024,2048]^T
    gemm_f16<128,0,0><<<dim3(8,16,1), 256, SMEM128>>>(
        p_ych, CED, 0, p_wh+OW_OUT, p_wh+OW_OUT, CED, out, CD, 0, CED, nullptr, nullptr);
}